// round 7
// baseline (speedup 1.0000x reference)
#include <cuda_runtime.h>

// ---------------------------------------------------------------------------
// WaveConv3d: 2-level db4 3D DWT (periodic, pad 8) -> per-voxel channel mix on
// the 8 coarsest bands -> inverse DWT (level-1 details zero -> lo-only).
// R7: R6 (ILP x2 x-pass, conflict-free smem orders, staged coalesced I/O) with
// the misalignment fixed: __align__(16) on shared arrays used via float4.
// ---------------------------------------------------------------------------

#define NV 12167            // 23^3

#define FLO {-0.010597401784997278f,  0.032883011666982945f,  0.030841381835986965f, \
             -0.18703481171888114f,  -0.02798376941698385f,   0.6308807679295904f,  \
              0.7148465705525415f,    0.23037781330885523f}
#define FHI { 0.23037781330885523f,  -0.7148465705525415f,    0.6308807679295904f,  \
              0.02798376941698385f,  -0.18703481171888114f,  -0.030841381835986965f,\
              0.032883011666982945f,  0.010597401784997278f}

// Scratch (max live = 8 bands * 320*23^3 = 31.1M floats)
__device__ float g_buf1[31147520];
__device__ float g_buf2[31147520];

// ---------------------------------------------------------------------------
// Forward DWT along a strided axis (x-pass), ILP x2: each thread computes two
// independent rows (g and g+half) with interleaved sliding windows.
// ---------------------------------------------------------------------------
template<int N, int INNER, bool HI>
__global__ void dwt_s(const float* __restrict__ in, float* __restrict__ olo,
                      float* __restrict__ ohi, unsigned half, unsigned total) {
    constexpr int K = (N + 8) / 2 + 1;
    const float LO[8] = FLO;
    const float HIc[8] = FHI;
    unsigned g = blockIdx.x * blockDim.x + threadIdx.x;
    if (g >= half) return;
    unsigned r0 = g;
    unsigned r1 = g + half;
    bool has1 = r1 < total;
    unsigned r1c = has1 ? r1 : r0;
    unsigned ii0 = r0 % INNER,  o0 = r0 / INNER;
    unsigned ii1 = r1c % INNER, o1 = r1c / INNER;
    const float* bp0 = in + (size_t)o0 * (N * INNER) + ii0;
    const float* bp1 = in + (size_t)o1 * (N * INNER) + ii1;
    float* lp0 = olo + (size_t)o0 * (K * INNER) + ii0;
    float* lp1 = olo + (size_t)o1 * (K * INNER) + ii1;
    float* hp0 = HI ? ohi + (size_t)o0 * (K * INNER) + ii0 : nullptr;
    float* hp1 = HI ? ohi + (size_t)o1 * (K * INNER) + ii1 : nullptr;

    float w0[8], w1[8];
#pragma unroll
    for (int t = 0; t < 8; t++) {
        w0[t] = bp0[(N - 8 + t) * INNER];
        w1[t] = bp1[(N - 8 + t) * INNER];
    }
#pragma unroll
    for (int j = 0; j < K; j++) {
        float alo0 = 0.f, ahi0 = 0.f, alo1 = 0.f, ahi1 = 0.f;
#pragma unroll
        for (int t = 0; t < 8; t++) {
            alo0 = fmaf(w0[t], LO[7 - t], alo0);
            alo1 = fmaf(w1[t], LO[7 - t], alo1);
            if (HI) {
                ahi0 = fmaf(w0[t], HIc[7 - t], ahi0);
                ahi1 = fmaf(w1[t], HIc[7 - t], ahi1);
            }
        }
        lp0[j * INNER] = alo0;
        if (HI) hp0[j * INNER] = ahi0;
        if (has1) {
            lp1[j * INNER] = alo1;
            if (HI) hp1[j * INNER] = ahi1;
        }
        if (j < K - 1) {
            int q0 = (2 * j) % N;        // compile-time after unroll
            int q1 = (2 * j + 1) % N;
#pragma unroll
            for (int t = 0; t < 6; t++) { w0[t] = w0[t + 2]; w1[t] = w1[t + 2]; }
            w0[6] = bp0[q0 * INNER];  w0[7] = bp0[q1 * INNER];
            w1[6] = bp1[q0 * INNER];  w1[7] = bp1[q1 * INNER];
        }
    }
}

// ---------------------------------------------------------------------------
// Inverse DWT along a strided axis (x-pass), ILP x2. Indices never wrap.
// ---------------------------------------------------------------------------
template<int K, int NOUT, int INNER, bool HI>
__global__ void idwt_s(const float* __restrict__ lo, const float* __restrict__ hi,
                       float* __restrict__ out, unsigned half, unsigned total) {
    const float LO[8] = FLO;
    const float HIc[8] = FHI;
    unsigned g = blockIdx.x * blockDim.x + threadIdx.x;
    if (g >= half) return;
    unsigned r0 = g;
    unsigned r1 = g + half;
    bool has1 = r1 < total;
    unsigned r1c = has1 ? r1 : r0;
    unsigned ii0 = r0 % INNER,  o0 = r0 / INNER;
    unsigned ii1 = r1c % INNER, o1 = r1c / INNER;
    const float* lp0 = lo + (size_t)o0 * (K * INNER) + ii0;
    const float* lp1 = lo + (size_t)o1 * (K * INNER) + ii1;
    const float* hp0 = HI ? hi + (size_t)o0 * (K * INNER) + ii0 : lp0;
    const float* hp1 = HI ? hi + (size_t)o1 * (K * INNER) + ii1 : lp1;
    float* op0 = out + (size_t)o0 * (NOUT * INNER) + ii0;
    float* op1 = out + (size_t)o1 * (NOUT * INNER) + ii1;

    float wl0[4], wh0[4], wl1[4], wh1[4];
#pragma unroll
    for (int d = 0; d < 4; d++) {
        wl0[d] = lp0[(1 + d) * INNER];
        wl1[d] = lp1[(1 + d) * INNER];
        if (HI) { wh0[d] = hp0[(1 + d) * INNER]; wh1[d] = hp1[(1 + d) * INNER]; }
    }
#pragma unroll
    for (int i = 0; i < NOUT; i++) {
        const int par = i & 1;
        float a0 = 0.f, a1 = 0.f;
#pragma unroll
        for (int d = 0; d < 4; d++) {
            a0 = fmaf(wl0[d], LO[2 * d + 1 - par], a0);
            a1 = fmaf(wl1[d], LO[2 * d + 1 - par], a1);
            if (HI) {
                a0 = fmaf(wh0[d], HIc[2 * d + 1 - par], a0);
                a1 = fmaf(wh1[d], HIc[2 * d + 1 - par], a1);
            }
        }
        op0[i * INNER] = a0;
        if (has1) op1[i * INNER] = a1;
        if (par && (i + 1 < NOUT)) {
            int jn = i / 2 + 5;
#pragma unroll
            for (int d = 0; d < 3; d++) {
                wl0[d] = wl0[d + 1];  wl1[d] = wl1[d + 1];
                if (HI) { wh0[d] = wh0[d + 1]; wh1[d] = wh1[d + 1]; }
            }
            wl0[3] = lp0[jn * INNER];
            wl1[3] = lp1[jn * INNER];
            if (HI) { wh0[3] = hp0[jn * INNER]; wh1[3] = hp1[jn * INNER]; }
        }
    }
}

// ---------------------------------------------------------------------------
// Level-1 forward, fused y+z, lo-only, paired outputs, staged output.
// 64x64 -> (y-DWT) 37x64 -> (z-DWT) 37x37. s1 rows padded to 65.
// ---------------------------------------------------------------------------
__global__ void f1_yz(const float* __restrict__ in, float* __restrict__ out) {
    __shared__ __align__(16) float s0[64 * 64];
    __shared__ float s1[37 * 65];
    __shared__ float sout[37 * 37];
    const float LO[8] = FLO;
    unsigned tid = threadIdx.x;
    size_t blk = blockIdx.x;
    const float4* gp4 = (const float4*)(in + blk * 4096);
    float4* s04 = (float4*)s0;
#pragma unroll 4
    for (int t = tid; t < 1024; t += 256) s04[t] = gp4[t];
    __syncthreads();
    // y-DWT pairs: z fastest (stride-1 smem, conflict-free).
    for (int u = tid; u < 19 * 64; u += 256) {
        int z = u & 63, jp = u >> 6;
        float w[10];
#pragma unroll
        for (int t = 0; t < 10; t++) {
            int q = (4 * jp - 8 + t) & 63;
            w[t] = s0[q * 64 + z];
        }
        float a0 = 0.f, a1 = 0.f;
#pragma unroll
        for (int s = 0; s < 8; s++) {
            a0 = fmaf(LO[s], w[7 - s], a0);
            a1 = fmaf(LO[s], w[9 - s], a1);
        }
        s1[(2 * jp) * 65 + z] = a0;
        if (2 * jp + 1 < 37) s1[(2 * jp + 1) * 65 + z] = a1;
    }
    __syncthreads();
    // z-DWT pairs: y fastest (stride-65 reads, stride-37 writes; conflict-free).
    for (int u = tid; u < 37 * 19; u += 256) {
        int y = u % 37, ph = u / 37;
        float w[10];
#pragma unroll
        for (int t = 0; t < 10; t++) {
            int q = (4 * ph - 8 + t) & 63;
            w[t] = s1[y * 65 + q];
        }
        float a0 = 0.f, a1 = 0.f;
#pragma unroll
        for (int s = 0; s < 8; s++) {
            a0 = fmaf(LO[s], w[7 - s], a0);
            a1 = fmaf(LO[s], w[9 - s], a1);
        }
        sout[y * 37 + 2 * ph] = a0;
        if (2 * ph + 1 < 37) sout[y * 37 + 2 * ph + 1] = a1;
    }
    __syncthreads();
    float* op = out + blk * 1369;
    for (int t = tid; t < 1369; t += 256) op[t] = sout[t];   // coalesced
}

// ---------------------------------------------------------------------------
// Level-2 forward, fused y+z, full (4 yz-bands), paired, staged output.
// ---------------------------------------------------------------------------
__global__ void f2_yz(const float* __restrict__ in, float* __restrict__ out,
                      long long S2) {
    __shared__ float s0[37 * 37];
    __shared__ float sl[23 * 37];
    __shared__ float sh[23 * 37];
    __shared__ float so[4 * 529];
    const float LO[8] = FLO;
    const float HIc[8] = FHI;
    unsigned tid = threadIdx.x;
    size_t blk = blockIdx.x;
    const float* gp = in + blk * 1369;
#pragma unroll 3
    for (int t = tid; t < 1369; t += 256) s0[t] = gp[t];
    __syncthreads();
    // y-DWT lo+hi, paired: z fastest (conflict-free).
    for (int u = tid; u < 12 * 37; u += 256) {
        int z = u % 37, jp = u / 37;
        float w[10];
#pragma unroll
        for (int t = 0; t < 10; t++) {
            int q = 4 * jp - 8 + t;
            if (q < 0) q += 37; else if (q >= 37) q -= 37;
            w[t] = s0[q * 37 + z];
        }
        float l0 = 0.f, h0 = 0.f, l1 = 0.f, h1 = 0.f;
#pragma unroll
        for (int s = 0; s < 8; s++) {
            l0 = fmaf(LO[s],  w[7 - s], l0);
            h0 = fmaf(HIc[s], w[7 - s], h0);
            l1 = fmaf(LO[s],  w[9 - s], l1);
            h1 = fmaf(HIc[s], w[9 - s], h1);
        }
        sl[(2 * jp) * 37 + z] = l0;
        sh[(2 * jp) * 37 + z] = h0;
        if (2 * jp + 1 < 23) {
            sl[(2 * jp + 1) * 37 + z] = l1;
            sh[(2 * jp + 1) * 37 + z] = h1;
        }
    }
    __syncthreads();
    // z-DWT on both, paired: y fastest (stride-37 reads, stride-23 writes).
    for (int u = tid; u < 23 * 12; u += 256) {
        int y = u % 23, ph = u / 23;
        float wl[10], wh[10];
#pragma unroll
        for (int t = 0; t < 10; t++) {
            int q = 4 * ph - 8 + t;
            if (q < 0) q += 37; else if (q >= 37) q -= 37;
            wl[t] = sl[y * 37 + q];
            wh[t] = sh[y * 37 + q];
        }
        float ll0 = 0.f, lh0 = 0.f, hl0 = 0.f, hh0 = 0.f;
        float ll1 = 0.f, lh1 = 0.f, hl1 = 0.f, hh1 = 0.f;
#pragma unroll
        for (int s = 0; s < 8; s++) {
            ll0 = fmaf(LO[s],  wl[7 - s], ll0);  lh0 = fmaf(HIc[s], wl[7 - s], lh0);
            hl0 = fmaf(LO[s],  wh[7 - s], hl0);  hh0 = fmaf(HIc[s], wh[7 - s], hh0);
            ll1 = fmaf(LO[s],  wl[9 - s], ll1);  lh1 = fmaf(HIc[s], wl[9 - s], lh1);
            hl1 = fmaf(LO[s],  wh[9 - s], hl1);  hh1 = fmaf(HIc[s], wh[9 - s], hh1);
        }
        int b0 = y * 23 + 2 * ph;
        so[b0]            = ll0;
        so[529 + b0]      = lh0;
        so[2 * 529 + b0]  = hl0;
        so[3 * 529 + b0]  = hh0;
        if (2 * ph + 1 < 23) {
            so[b0 + 1]           = ll1;
            so[529 + b0 + 1]     = lh1;
            so[2 * 529 + b0 + 1] = hl1;
            so[3 * 529 + b0 + 1] = hh1;
        }
    }
    __syncthreads();
    for (int t = tid; t < 4 * 529; t += 256) {               // coalesced
        int slot = t / 529, r = t % 529;
        out[(size_t)slot * S2 + blk * 529 + r] = so[t];
    }
}

// ---------------------------------------------------------------------------
// Level-2 inverse, fused z+y, full, paired, staged output.
// ---------------------------------------------------------------------------
__global__ void i2_yz(const float* __restrict__ in, float* __restrict__ out,
                      long long S2) {
    __shared__ float si[4 * 529];
    __shared__ float sl[23 * 37];
    __shared__ float sh[23 * 37];
    __shared__ float sout[37 * 37];
    const float LO[8] = FLO;
    const float HIc[8] = FHI;
    unsigned tid = threadIdx.x;
    size_t blk = blockIdx.x;
    for (int t = tid; t < 4 * 529; t += 256) {
        int slot = t / 529, r = t % 529;
        si[t] = in[(size_t)slot * S2 + blk * 529 + r];
    }
    __syncthreads();
    // z-IDWT, both dy rows, paired: y fastest (stride-23 reads, stride-37 writes).
    for (int u = tid; u < 23 * 19; u += 256) {
        int y = u % 23, m = u / 23;
        int js = m + 1;
        float a0 = 0.f, a1 = 0.f, b0 = 0.f, b1 = 0.f;
#pragma unroll
        for (int d = 0; d < 4; d++) {
            int q = y * 23 + js + d;
            float v0 = si[q],           v1 = si[529 + q];
            float v2 = si[2 * 529 + q], v3 = si[3 * 529 + q];
            a0 = fmaf(v0, LO[2 * d + 1], a0);  a0 = fmaf(v1, HIc[2 * d + 1], a0);
            a1 = fmaf(v0, LO[2 * d],     a1);  a1 = fmaf(v1, HIc[2 * d],     a1);
            b0 = fmaf(v2, LO[2 * d + 1], b0);  b0 = fmaf(v3, HIc[2 * d + 1], b0);
            b1 = fmaf(v2, LO[2 * d],     b1);  b1 = fmaf(v3, HIc[2 * d],     b1);
        }
        sl[y * 37 + 2 * m] = a0;  sh[y * 37 + 2 * m] = b0;
        if (2 * m + 1 < 37) {
            sl[y * 37 + 2 * m + 1] = a1;  sh[y * 37 + 2 * m + 1] = b1;
        }
    }
    __syncthreads();
    // y-IDWT, paired: z fastest (stride-1 reads/writes).
    for (int u = tid; u < 19 * 37; u += 256) {
        int z = u % 37, m = u / 37;
        int js = m + 1;
        float a0 = 0.f, a1 = 0.f;
#pragma unroll
        for (int d = 0; d < 4; d++) {
            float vl = sl[(js + d) * 37 + z];
            float vh = sh[(js + d) * 37 + z];
            a0 = fmaf(vl, LO[2 * d + 1], a0);  a0 = fmaf(vh, HIc[2 * d + 1], a0);
            a1 = fmaf(vl, LO[2 * d],     a1);  a1 = fmaf(vh, HIc[2 * d],     a1);
        }
        sout[(2 * m) * 37 + z] = a0;
        if (2 * m + 1 < 37) sout[(2 * m + 1) * 37 + z] = a1;
    }
    __syncthreads();
    float* op = out + blk * 1369;
    for (int t = tid; t < 1369; t += 256) op[t] = sout[t];   // coalesced
}

// ---------------------------------------------------------------------------
// Level-1 inverse, fused z+y, lo-only, paired, staged float4 output.
// ---------------------------------------------------------------------------
__global__ void i1_yz(const float* __restrict__ in, float* __restrict__ out) {
    __shared__ float s0[37 * 37];
    __shared__ float s1[37 * 65];
    __shared__ __align__(16) float sout[64 * 64];
    const float LO[8] = FLO;
    unsigned tid = threadIdx.x;
    size_t blk = blockIdx.x;
    const float* gp = in + blk * 1369;
#pragma unroll 3
    for (int t = tid; t < 1369; t += 256) s0[t] = gp[t];
    __syncthreads();
    // z-IDWT, paired: y fastest (stride-37 reads, stride-65 writes).
    for (int u = tid; u < 37 * 32; u += 256) {
        int y = u % 37, m = u / 37;
        int js = m + 1;
        float a0 = 0.f, a1 = 0.f;
#pragma unroll
        for (int d = 0; d < 4; d++) {
            float v = s0[y * 37 + js + d];
            a0 = fmaf(v, LO[2 * d + 1], a0);
            a1 = fmaf(v, LO[2 * d],     a1);
        }
        s1[y * 65 + 2 * m]     = a0;
        s1[y * 65 + 2 * m + 1] = a1;
    }
    __syncthreads();
    // y-IDWT, paired: z fastest (stride-1).
    for (int u = tid; u < 32 * 64; u += 256) {
        int z = u & 63, m = u >> 6;
        int js = m + 1;
        float a0 = 0.f, a1 = 0.f;
#pragma unroll
        for (int d = 0; d < 4; d++) {
            float v = s1[(js + d) * 65 + z];
            a0 = fmaf(v, LO[2 * d + 1], a0);
            a1 = fmaf(v, LO[2 * d],     a1);
        }
        sout[(2 * m) * 64 + z]     = a0;
        sout[(2 * m + 1) * 64 + z] = a1;
    }
    __syncthreads();
    float4* op4 = (float4*)(out + blk * 4096);
    const float4* so4 = (const float4*)sout;
#pragma unroll 4
    for (int t = tid; t < 1024; t += 256) op4[t] = so4[t];   // coalesced f4
}

// ---------------------------------------------------------------------------
// Channel mix, ALL 8 bands in one launch (blockIdx.y = band).
// ---------------------------------------------------------------------------
__global__ void chanmix_all(const float* __restrict__ in,
                            float* __restrict__ out, long long SBl,
                            const float* __restrict__ w0, const float* __restrict__ w1,
                            const float* __restrict__ w2, const float* __restrict__ w3,
                            const float* __restrict__ w4, const float* __restrict__ w5,
                            const float* __restrict__ w6, const float* __restrict__ w7) {
    __shared__ float s_in[320][32];
    int k = blockIdx.y;
    const float* w;
    switch (k) {
        case 0: w = w0; break; case 1: w = w1; break;
        case 2: w = w2; break; case 3: w = w3; break;
        case 4: w = w4; break; case 5: w = w5; break;
        case 6: w = w6; break; default: w = w7; break;
    }
    const float* bin  = in  + (long long)k * SBl;
    float*       bout = out + (long long)k * SBl;

    int lane = threadIdx.x;
    int ty   = threadIdx.y;
    int v    = blockIdx.x * 32 + lane;
    bool valid = v < NV;
    int vc = valid ? v : (NV - 1);

    for (int r = ty; r < 320; r += 8)
        s_in[r][lane] = bin[(long long)r * NV + vc];
    __syncthreads();

    float acc[5][8];
#pragma unroll
    for (int a = 0; a < 5; a++)
#pragma unroll
        for (int b = 0; b < 8; b++) acc[a][b] = 0.f;

#pragma unroll 2
    for (int i = 0; i < 40; i += 2) {
        float xv0[8], xv1[8];
#pragma unroll
        for (int b = 0; b < 8; b++) {
            xv0[b] = s_in[b * 40 + i][lane];
            xv1[b] = s_in[b * 40 + i + 1][lane];
        }
        float wv0[5], wv1[5];
#pragma unroll
        for (int oo = 0; oo < 5; oo++) {
            int o = ty + oo * 8;
            wv0[oo] = w[((long long)i * 40 + o) * NV + vc];
            wv1[oo] = w[((long long)(i + 1) * 40 + o) * NV + vc];
        }
#pragma unroll
        for (int oo = 0; oo < 5; oo++)
#pragma unroll
            for (int b = 0; b < 8; b++) {
                acc[oo][b] = fmaf(xv0[b], wv0[oo], acc[oo][b]);
                acc[oo][b] = fmaf(xv1[b], wv1[oo], acc[oo][b]);
            }
    }
    if (!valid) return;
#pragma unroll
    for (int oo = 0; oo < 5; oo++) {
        int o = ty + oo * 8;
#pragma unroll
        for (int b = 0; b < 8; b++)
            bout[((long long)b * 40 + o) * NV + v] = acc[oo][b];
    }
}

// ---------------------------------------------------------------------------
extern "C" void kernel_launch(void* const* d_in, const int* in_sizes, int n_in,
                              void* d_out, int out_size) {
    const float* x = (const float*)d_in[0];
    float* out = (float*)d_out;

    float *b1, *b2;
    cudaGetSymbolAddress((void**)&b1, g_buf1);
    cudaGetSymbolAddress((void**)&b2, g_buf2);

    const long long S2  = 6263360LL;   // 320*37*23*23 (per yz-band volume)
    const long long SBl = 3893440LL;   // 320*23*23*23 (per final band volume)

    auto g = [](unsigned t) { return (t + 255u) / 256u; };

    // --- Level-1 forward: fused yz (lo), then x (lo, ILP2) -------------------
    f1_yz<<<320 * 64, 256>>>(x, b1);                        // -> (320,64,37,37)
    { unsigned T = 320u * 1369u, H = (T + 1) / 2;           // -> (320,37,37,37)
      dwt_s<64, 1369, false><<<g(H), 256>>>(b1, b2, nullptr, H, T); }

    // --- Level-2 forward: fused yz (4 bands), then x (lo+hi, ILP2) ----------
    f2_yz<<<320 * 37, 256>>>(b2, b1, S2);                   // -> 4x(320,37,23,23)
    { unsigned T = 1280u * 529u, H = (T + 1) / 2;           // -> 8x(320,23,23,23)
      dwt_s<37, 529, true><<<g(H), 256>>>(b1, b2, b2 + 4 * SBl, H, T); }

    // --- Channel mix: all 8 bands in one launch (slot == weight index k) ----
    chanmix_all<<<dim3((NV + 31) / 32, 8), dim3(32, 8)>>>(
        b2, b1, SBl,
        (const float*)d_in[1], (const float*)d_in[2],
        (const float*)d_in[3], (const float*)d_in[4],
        (const float*)d_in[5], (const float*)d_in[6],
        (const float*)d_in[7], (const float*)d_in[8]);

    // --- Level-2 inverse: x (lo+hi, ILP2), then fused zy --------------------
    { unsigned T = 1280u * 529u, H = (T + 1) / 2;           // -> 4x(320,37,23,23)
      idwt_s<23, 37, 529, true><<<g(H), 256>>>(b1, b1 + 4 * SBl, b2, H, T); }
    i2_yz<<<320 * 37, 256>>>(b2, b1, S2);                   // -> (320,37,37,37)

    // --- Level-1 inverse: x (lo, ILP2), then fused zy (lo) -------------------
    { unsigned T = 320u * 1369u, H = (T + 1) / 2;           // -> (320,64,37,37)
      idwt_s<37, 64, 1369, false><<<g(H), 256>>>(b1, nullptr, b2, H, T); }
    i1_yz<<<320 * 64, 256>>>(b2, out);                      // -> (320,64,64,64)
}

// round 8
// speedup vs baseline: 1.0369x; 1.0369x over previous
#include <cuda_runtime.h>

// ---------------------------------------------------------------------------
// WaveConv3d: 2-level db4 3D DWT (periodic, pad 8) -> per-voxel channel mix on
// the 8 coarsest bands -> inverse DWT (level-1 details zero -> lo-only).
// R8: strided x-pass kernels reverted to R5 single-row form (ILP x2 regressed
// via register pressure); fused yz kernels keep R7's conflict-free loop orders
// and staged coalesced global I/O.
// ---------------------------------------------------------------------------

#define NV 12167            // 23^3

#define FLO {-0.010597401784997278f,  0.032883011666982945f,  0.030841381835986965f, \
             -0.18703481171888114f,  -0.02798376941698385f,   0.6308807679295904f,  \
              0.7148465705525415f,    0.23037781330885523f}
#define FHI { 0.23037781330885523f,  -0.7148465705525415f,    0.6308807679295904f,  \
              0.02798376941698385f,  -0.18703481171888114f,  -0.030841381835986965f,\
              0.032883011666982945f,  0.010597401784997278f}

// Scratch (max live = 8 bands * 320*23^3 = 31.1M floats)
__device__ float g_buf1[31147520];
__device__ float g_buf2[31147520];

// ---------------------------------------------------------------------------
// Forward DWT along a strided axis (x-pass). (outer, N, INNER) -> (outer, K, INNER).
// One thread per row: sliding 8-window, fully unrolled. 40 regs, high occ.
// ---------------------------------------------------------------------------
template<int N, int INNER, bool HI>
__global__ void dwt_s(const float* __restrict__ in, float* __restrict__ olo,
                      float* __restrict__ ohi, unsigned total) {
    constexpr int K = (N + 8) / 2 + 1;
    const float LO[8] = FLO;
    const float HIc[8] = FHI;
    unsigned g = blockIdx.x * blockDim.x + threadIdx.x;
    if (g >= total) return;
    unsigned ii = g % INNER;
    unsigned o  = g / INNER;
    const float* bp = in  + (size_t)o * (N * INNER) + ii;
    float*       lp = olo + (size_t)o * (K * INNER) + ii;
    float*       hp = HI ? ohi + (size_t)o * (K * INNER) + ii : nullptr;

    float w[8];
#pragma unroll
    for (int t = 0; t < 8; t++) w[t] = bp[(N - 8 + t) * INNER];

#pragma unroll
    for (int j = 0; j < K; j++) {
        float alo = 0.f, ahi = 0.f;
#pragma unroll
        for (int t = 0; t < 8; t++) {
            alo = fmaf(w[t], LO[7 - t], alo);
            if (HI) ahi = fmaf(w[t], HIc[7 - t], ahi);
        }
        lp[j * INNER] = alo;
        if (HI) hp[j * INNER] = ahi;
        if (j < K - 1) {
            int q0 = (2 * j) % N;        // compile-time after unroll
            int q1 = (2 * j + 1) % N;
#pragma unroll
            for (int t = 0; t < 6; t++) w[t] = w[t + 2];
            w[6] = bp[q0 * INNER];
            w[7] = bp[q1 * INNER];
        }
    }
}

// ---------------------------------------------------------------------------
// Inverse DWT along a strided axis (x-pass). Indices never wrap for our sizes.
// ---------------------------------------------------------------------------
template<int K, int NOUT, int INNER, bool HI>
__global__ void idwt_s(const float* __restrict__ lo, const float* __restrict__ hi,
                       float* __restrict__ out, unsigned total) {
    const float LO[8] = FLO;
    const float HIc[8] = FHI;
    unsigned g = blockIdx.x * blockDim.x + threadIdx.x;
    if (g >= total) return;
    unsigned ii = g % INNER;
    unsigned o  = g / INNER;
    const float* lp = lo + (size_t)o * (K * INNER) + ii;
    const float* hp = HI ? hi + (size_t)o * (K * INNER) + ii : lp;
    float*       op = out + (size_t)o * (NOUT * INNER) + ii;

    float wl[4], wh[4];
#pragma unroll
    for (int d = 0; d < 4; d++) {
        wl[d] = lp[(1 + d) * INNER];
        if (HI) wh[d] = hp[(1 + d) * INNER];
    }
#pragma unroll
    for (int i = 0; i < NOUT; i++) {
        const int par = i & 1;
        float acc = 0.f;
#pragma unroll
        for (int d = 0; d < 4; d++) {
            acc = fmaf(wl[d], LO[2 * d + 1 - par], acc);
            if (HI) acc = fmaf(wh[d], HIc[2 * d + 1 - par], acc);
        }
        op[i * INNER] = acc;
        if (par && (i + 1 < NOUT)) {
            int jn = i / 2 + 5;
#pragma unroll
            for (int d = 0; d < 3; d++) {
                wl[d] = wl[d + 1];
                if (HI) wh[d] = wh[d + 1];
            }
            wl[3] = lp[jn * INNER];
            if (HI) wh[3] = hp[jn * INNER];
        }
    }
}

// ---------------------------------------------------------------------------
// Level-1 forward, fused y+z, lo-only, paired outputs, staged output.
// 64x64 -> (y-DWT) 37x64 -> (z-DWT) 37x37. s1 rows padded to 65.
// ---------------------------------------------------------------------------
__global__ void f1_yz(const float* __restrict__ in, float* __restrict__ out) {
    __shared__ __align__(16) float s0[64 * 64];
    __shared__ float s1[37 * 65];
    __shared__ float sout[37 * 37];
    const float LO[8] = FLO;
    unsigned tid = threadIdx.x;
    size_t blk = blockIdx.x;
    const float4* gp4 = (const float4*)(in + blk * 4096);
    float4* s04 = (float4*)s0;
#pragma unroll 4
    for (int t = tid; t < 1024; t += 256) s04[t] = gp4[t];
    __syncthreads();
    // y-DWT pairs: z fastest (stride-1 smem, conflict-free).
    for (int u = tid; u < 19 * 64; u += 256) {
        int z = u & 63, jp = u >> 6;
        float w[10];
#pragma unroll
        for (int t = 0; t < 10; t++) {
            int q = (4 * jp - 8 + t) & 63;
            w[t] = s0[q * 64 + z];
        }
        float a0 = 0.f, a1 = 0.f;
#pragma unroll
        for (int s = 0; s < 8; s++) {
            a0 = fmaf(LO[s], w[7 - s], a0);
            a1 = fmaf(LO[s], w[9 - s], a1);
        }
        s1[(2 * jp) * 65 + z] = a0;
        if (2 * jp + 1 < 37) s1[(2 * jp + 1) * 65 + z] = a1;
    }
    __syncthreads();
    // z-DWT pairs: y fastest (stride-65 reads, stride-37 writes; conflict-free).
    for (int u = tid; u < 37 * 19; u += 256) {
        int y = u % 37, ph = u / 37;
        float w[10];
#pragma unroll
        for (int t = 0; t < 10; t++) {
            int q = (4 * ph - 8 + t) & 63;
            w[t] = s1[y * 65 + q];
        }
        float a0 = 0.f, a1 = 0.f;
#pragma unroll
        for (int s = 0; s < 8; s++) {
            a0 = fmaf(LO[s], w[7 - s], a0);
            a1 = fmaf(LO[s], w[9 - s], a1);
        }
        sout[y * 37 + 2 * ph] = a0;
        if (2 * ph + 1 < 37) sout[y * 37 + 2 * ph + 1] = a1;
    }
    __syncthreads();
    float* op = out + blk * 1369;
    for (int t = tid; t < 1369; t += 256) op[t] = sout[t];   // coalesced
}

// ---------------------------------------------------------------------------
// Level-2 forward, fused y+z, full (4 yz-bands), paired, staged output.
// ---------------------------------------------------------------------------
__global__ void f2_yz(const float* __restrict__ in, float* __restrict__ out,
                      long long S2) {
    __shared__ float s0[37 * 37];
    __shared__ float sl[23 * 37];
    __shared__ float sh[23 * 37];
    __shared__ float so[4 * 529];
    const float LO[8] = FLO;
    const float HIc[8] = FHI;
    unsigned tid = threadIdx.x;
    size_t blk = blockIdx.x;
    const float* gp = in + blk * 1369;
#pragma unroll 3
    for (int t = tid; t < 1369; t += 256) s0[t] = gp[t];
    __syncthreads();
    // y-DWT lo+hi, paired: z fastest (conflict-free).
    for (int u = tid; u < 12 * 37; u += 256) {
        int z = u % 37, jp = u / 37;
        float w[10];
#pragma unroll
        for (int t = 0; t < 10; t++) {
            int q = 4 * jp - 8 + t;
            if (q < 0) q += 37; else if (q >= 37) q -= 37;
            w[t] = s0[q * 37 + z];
        }
        float l0 = 0.f, h0 = 0.f, l1 = 0.f, h1 = 0.f;
#pragma unroll
        for (int s = 0; s < 8; s++) {
            l0 = fmaf(LO[s],  w[7 - s], l0);
            h0 = fmaf(HIc[s], w[7 - s], h0);
            l1 = fmaf(LO[s],  w[9 - s], l1);
            h1 = fmaf(HIc[s], w[9 - s], h1);
        }
        sl[(2 * jp) * 37 + z] = l0;
        sh[(2 * jp) * 37 + z] = h0;
        if (2 * jp + 1 < 23) {
            sl[(2 * jp + 1) * 37 + z] = l1;
            sh[(2 * jp + 1) * 37 + z] = h1;
        }
    }
    __syncthreads();
    // z-DWT on both, paired: y fastest (stride-37 reads, stride-23 writes).
    for (int u = tid; u < 23 * 12; u += 256) {
        int y = u % 23, ph = u / 23;
        float wl[10], wh[10];
#pragma unroll
        for (int t = 0; t < 10; t++) {
            int q = 4 * ph - 8 + t;
            if (q < 0) q += 37; else if (q >= 37) q -= 37;
            wl[t] = sl[y * 37 + q];
            wh[t] = sh[y * 37 + q];
        }
        float ll0 = 0.f, lh0 = 0.f, hl0 = 0.f, hh0 = 0.f;
        float ll1 = 0.f, lh1 = 0.f, hl1 = 0.f, hh1 = 0.f;
#pragma unroll
        for (int s = 0; s < 8; s++) {
            ll0 = fmaf(LO[s],  wl[7 - s], ll0);  lh0 = fmaf(HIc[s], wl[7 - s], lh0);
            hl0 = fmaf(LO[s],  wh[7 - s], hl0);  hh0 = fmaf(HIc[s], wh[7 - s], hh0);
            ll1 = fmaf(LO[s],  wl[9 - s], ll1);  lh1 = fmaf(HIc[s], wl[9 - s], lh1);
            hl1 = fmaf(LO[s],  wh[9 - s], hl1);  hh1 = fmaf(HIc[s], wh[9 - s], hh1);
        }
        int b0 = y * 23 + 2 * ph;
        so[b0]            = ll0;
        so[529 + b0]      = lh0;
        so[2 * 529 + b0]  = hl0;
        so[3 * 529 + b0]  = hh0;
        if (2 * ph + 1 < 23) {
            so[b0 + 1]           = ll1;
            so[529 + b0 + 1]     = lh1;
            so[2 * 529 + b0 + 1] = hl1;
            so[3 * 529 + b0 + 1] = hh1;
        }
    }
    __syncthreads();
    for (int t = tid; t < 4 * 529; t += 256) {               // coalesced
        int slot = t / 529, r = t % 529;
        out[(size_t)slot * S2 + blk * 529 + r] = so[t];
    }
}

// ---------------------------------------------------------------------------
// Level-2 inverse, fused z+y, full, paired, staged output.
// ---------------------------------------------------------------------------
__global__ void i2_yz(const float* __restrict__ in, float* __restrict__ out,
                      long long S2) {
    __shared__ float si[4 * 529];
    __shared__ float sl[23 * 37];
    __shared__ float sh[23 * 37];
    __shared__ float sout[37 * 37];
    const float LO[8] = FLO;
    const float HIc[8] = FHI;
    unsigned tid = threadIdx.x;
    size_t blk = blockIdx.x;
    for (int t = tid; t < 4 * 529; t += 256) {
        int slot = t / 529, r = t % 529;
        si[t] = in[(size_t)slot * S2 + blk * 529 + r];
    }
    __syncthreads();
    // z-IDWT, both dy rows, paired: y fastest (stride-23 reads, stride-37 writes).
    for (int u = tid; u < 23 * 19; u += 256) {
        int y = u % 23, m = u / 23;
        int js = m + 1;
        float a0 = 0.f, a1 = 0.f, b0 = 0.f, b1 = 0.f;
#pragma unroll
        for (int d = 0; d < 4; d++) {
            int q = y * 23 + js + d;
            float v0 = si[q],           v1 = si[529 + q];
            float v2 = si[2 * 529 + q], v3 = si[3 * 529 + q];
            a0 = fmaf(v0, LO[2 * d + 1], a0);  a0 = fmaf(v1, HIc[2 * d + 1], a0);
            a1 = fmaf(v0, LO[2 * d],     a1);  a1 = fmaf(v1, HIc[2 * d],     a1);
            b0 = fmaf(v2, LO[2 * d + 1], b0);  b0 = fmaf(v3, HIc[2 * d + 1], b0);
            b1 = fmaf(v2, LO[2 * d],     b1);  b1 = fmaf(v3, HIc[2 * d],     b1);
        }
        sl[y * 37 + 2 * m] = a0;  sh[y * 37 + 2 * m] = b0;
        if (2 * m + 1 < 37) {
            sl[y * 37 + 2 * m + 1] = a1;  sh[y * 37 + 2 * m + 1] = b1;
        }
    }
    __syncthreads();
    // y-IDWT, paired: z fastest (stride-1 reads/writes).
    for (int u = tid; u < 19 * 37; u += 256) {
        int z = u % 37, m = u / 37;
        int js = m + 1;
        float a0 = 0.f, a1 = 0.f;
#pragma unroll
        for (int d = 0; d < 4; d++) {
            float vl = sl[(js + d) * 37 + z];
            float vh = sh[(js + d) * 37 + z];
            a0 = fmaf(vl, LO[2 * d + 1], a0);  a0 = fmaf(vh, HIc[2 * d + 1], a0);
            a1 = fmaf(vl, LO[2 * d],     a1);  a1 = fmaf(vh, HIc[2 * d],     a1);
        }
        sout[(2 * m) * 37 + z] = a0;
        if (2 * m + 1 < 37) sout[(2 * m + 1) * 37 + z] = a1;
    }
    __syncthreads();
    float* op = out + blk * 1369;
    for (int t = tid; t < 1369; t += 256) op[t] = sout[t];   // coalesced
}

// ---------------------------------------------------------------------------
// Level-1 inverse, fused z+y, lo-only, paired, staged float4 output.
// ---------------------------------------------------------------------------
__global__ void i1_yz(const float* __restrict__ in, float* __restrict__ out) {
    __shared__ float s0[37 * 37];
    __shared__ float s1[37 * 65];
    __shared__ __align__(16) float sout[64 * 64];
    const float LO[8] = FLO;
    unsigned tid = threadIdx.x;
    size_t blk = blockIdx.x;
    const float* gp = in + blk * 1369;
#pragma unroll 3
    for (int t = tid; t < 1369; t += 256) s0[t] = gp[t];
    __syncthreads();
    // z-IDWT, paired: y fastest (stride-37 reads, stride-65 writes).
    for (int u = tid; u < 37 * 32; u += 256) {
        int y = u % 37, m = u / 37;
        int js = m + 1;
        float a0 = 0.f, a1 = 0.f;
#pragma unroll
        for (int d = 0; d < 4; d++) {
            float v = s0[y * 37 + js + d];
            a0 = fmaf(v, LO[2 * d + 1], a0);
            a1 = fmaf(v, LO[2 * d],     a1);
        }
        s1[y * 65 + 2 * m]     = a0;
        s1[y * 65 + 2 * m + 1] = a1;
    }
    __syncthreads();
    // y-IDWT, paired: z fastest (stride-1).
    for (int u = tid; u < 32 * 64; u += 256) {
        int z = u & 63, m = u >> 6;
        int js = m + 1;
        float a0 = 0.f, a1 = 0.f;
#pragma unroll
        for (int d = 0; d < 4; d++) {
            float v = s1[(js + d) * 65 + z];
            a0 = fmaf(v, LO[2 * d + 1], a0);
            a1 = fmaf(v, LO[2 * d],     a1);
        }
        sout[(2 * m) * 64 + z]     = a0;
        sout[(2 * m + 1) * 64 + z] = a1;
    }
    __syncthreads();
    float4* op4 = (float4*)(out + blk * 4096);
    const float4* so4 = (const float4*)sout;
#pragma unroll 4
    for (int t = tid; t < 1024; t += 256) op4[t] = so4[t];   // coalesced f4
}

// ---------------------------------------------------------------------------
// Channel mix, ALL 8 bands in one launch (blockIdx.y = band).
// ---------------------------------------------------------------------------
__global__ void chanmix_all(const float* __restrict__ in,
                            float* __restrict__ out, long long SBl,
                            const float* __restrict__ w0, const float* __restrict__ w1,
                            const float* __restrict__ w2, const float* __restrict__ w3,
                            const float* __restrict__ w4, const float* __restrict__ w5,
                            const float* __restrict__ w6, const float* __restrict__ w7) {
    __shared__ float s_in[320][32];
    int k = blockIdx.y;
    const float* w;
    switch (k) {
        case 0: w = w0; break; case 1: w = w1; break;
        case 2: w = w2; break; case 3: w = w3; break;
        case 4: w = w4; break; case 5: w = w5; break;
        case 6: w = w6; break; default: w = w7; break;
    }
    const float* bin  = in  + (long long)k * SBl;
    float*       bout = out + (long long)k * SBl;

    int lane = threadIdx.x;
    int ty   = threadIdx.y;
    int v    = blockIdx.x * 32 + lane;
    bool valid = v < NV;
    int vc = valid ? v : (NV - 1);

    for (int r = ty; r < 320; r += 8)
        s_in[r][lane] = bin[(long long)r * NV + vc];
    __syncthreads();

    float acc[5][8];
#pragma unroll
    for (int a = 0; a < 5; a++)
#pragma unroll
        for (int b = 0; b < 8; b++) acc[a][b] = 0.f;

#pragma unroll 2
    for (int i = 0; i < 40; i += 2) {
        float xv0[8], xv1[8];
#pragma unroll
        for (int b = 0; b < 8; b++) {
            xv0[b] = s_in[b * 40 + i][lane];
            xv1[b] = s_in[b * 40 + i + 1][lane];
        }
        float wv0[5], wv1[5];
#pragma unroll
        for (int oo = 0; oo < 5; oo++) {
            int o = ty + oo * 8;
            wv0[oo] = w[((long long)i * 40 + o) * NV + vc];
            wv1[oo] = w[((long long)(i + 1) * 40 + o) * NV + vc];
        }
#pragma unroll
        for (int oo = 0; oo < 5; oo++)
#pragma unroll
            for (int b = 0; b < 8; b++) {
                acc[oo][b] = fmaf(xv0[b], wv0[oo], acc[oo][b]);
                acc[oo][b] = fmaf(xv1[b], wv1[oo], acc[oo][b]);
            }
    }
    if (!valid) return;
#pragma unroll
    for (int oo = 0; oo < 5; oo++) {
        int o = ty + oo * 8;
#pragma unroll
        for (int b = 0; b < 8; b++)
            bout[((long long)b * 40 + o) * NV + v] = acc[oo][b];
    }
}

// ---------------------------------------------------------------------------
extern "C" void kernel_launch(void* const* d_in, const int* in_sizes, int n_in,
                              void* d_out, int out_size) {
    const float* x = (const float*)d_in[0];
    float* out = (float*)d_out;

    float *b1, *b2;
    cudaGetSymbolAddress((void**)&b1, g_buf1);
    cudaGetSymbolAddress((void**)&b2, g_buf2);

    const long long S2  = 6263360LL;   // 320*37*23*23 (per yz-band volume)
    const long long SBl = 3893440LL;   // 320*23*23*23 (per final band volume)

    auto g = [](unsigned t) { return (t + 255u) / 256u; };

    // --- Level-1 forward: fused yz (lo), then x (lo) ------------------------
    f1_yz<<<320 * 64, 256>>>(x, b1);                        // -> (320,64,37,37)
    { unsigned T = 320u * 1369u;                            // -> (320,37,37,37)
      dwt_s<64, 1369, false><<<g(T), 256>>>(b1, b2, nullptr, T); }

    // --- Level-2 forward: fused yz (4 bands), then x (lo+hi over all 4) -----
    f2_yz<<<320 * 37, 256>>>(b2, b1, S2);                   // -> 4x(320,37,23,23)
    { unsigned T = 1280u * 529u;                            // -> 8x(320,23,23,23)
      dwt_s<37, 529, true><<<g(T), 256>>>(b1, b2, b2 + 4 * SBl, T); }

    // --- Channel mix: all 8 bands in one launch (slot == weight index k) ----
    chanmix_all<<<dim3((NV + 31) / 32, 8), dim3(32, 8)>>>(
        b2, b1, SBl,
        (const float*)d_in[1], (const float*)d_in[2],
        (const float*)d_in[3], (const float*)d_in[4],
        (const float*)d_in[5], (const float*)d_in[6],
        (const float*)d_in[7], (const float*)d_in[8]);

    // --- Level-2 inverse: x (lo+hi over all 4), then fused zy ---------------
    { unsigned T = 1280u * 529u;                            // -> 4x(320,37,23,23)
      idwt_s<23, 37, 529, true><<<g(T), 256>>>(b1, b1 + 4 * SBl, b2, T); }
    i2_yz<<<320 * 37, 256>>>(b2, b1, S2);                   // -> (320,37,37,37)

    // --- Level-1 inverse: x (lo), then fused zy (lo) -------------------------
    { unsigned T = 320u * 1369u;                            // -> (320,64,37,37)
      idwt_s<37, 64, 1369, false><<<g(T), 256>>>(b1, nullptr, b2, T); }
    i1_yz<<<320 * 64, 256>>>(b2, out);                      // -> (320,64,64,64)
}

// round 9
// speedup vs baseline: 1.1105x; 1.0710x over previous
#include <cuda_runtime.h>

// ---------------------------------------------------------------------------
// WaveConv3d: 2-level db4 3D DWT (periodic, pad 8) -> per-voxel channel mix on
// the 8 coarsest bands -> inverse DWT (level-1 details zero -> lo-only).
// R9: yz kernels reverted to the proven R5 forms; level-1 inverse x-IDWT fused
// into the zy kernel (i1x_yz, 4 output x-slices per block, 5-slice reads),
// eliminating the (320,64,37,37) intermediate (saves ~224MB of traffic).
// ---------------------------------------------------------------------------

#define NV 12167            // 23^3

#define FLO {-0.010597401784997278f,  0.032883011666982945f,  0.030841381835986965f, \
             -0.18703481171888114f,  -0.02798376941698385f,   0.6308807679295904f,  \
              0.7148465705525415f,    0.23037781330885523f}
#define FHI { 0.23037781330885523f,  -0.7148465705525415f,    0.6308807679295904f,  \
              0.02798376941698385f,  -0.18703481171888114f,  -0.030841381835986965f,\
              0.032883011666982945f,  0.010597401784997278f}

// Scratch (max live = 8 bands * 320*23^3 = 31.1M floats)
__device__ float g_buf1[31147520];
__device__ float g_buf2[31147520];

// ---------------------------------------------------------------------------
// Forward DWT along a strided axis (x-pass). One thread per row, sliding window.
// ---------------------------------------------------------------------------
template<int N, int INNER, bool HI>
__global__ void dwt_s(const float* __restrict__ in, float* __restrict__ olo,
                      float* __restrict__ ohi, unsigned total) {
    constexpr int K = (N + 8) / 2 + 1;
    const float LO[8] = FLO;
    const float HIc[8] = FHI;
    unsigned g = blockIdx.x * blockDim.x + threadIdx.x;
    if (g >= total) return;
    unsigned ii = g % INNER;
    unsigned o  = g / INNER;
    const float* bp = in  + (size_t)o * (N * INNER) + ii;
    float*       lp = olo + (size_t)o * (K * INNER) + ii;
    float*       hp = HI ? ohi + (size_t)o * (K * INNER) + ii : nullptr;

    float w[8];
#pragma unroll
    for (int t = 0; t < 8; t++) w[t] = bp[(N - 8 + t) * INNER];

#pragma unroll
    for (int j = 0; j < K; j++) {
        float alo = 0.f, ahi = 0.f;
#pragma unroll
        for (int t = 0; t < 8; t++) {
            alo = fmaf(w[t], LO[7 - t], alo);
            if (HI) ahi = fmaf(w[t], HIc[7 - t], ahi);
        }
        lp[j * INNER] = alo;
        if (HI) hp[j * INNER] = ahi;
        if (j < K - 1) {
            int q0 = (2 * j) % N;
            int q1 = (2 * j + 1) % N;
#pragma unroll
            for (int t = 0; t < 6; t++) w[t] = w[t + 2];
            w[6] = bp[q0 * INNER];
            w[7] = bp[q1 * INNER];
        }
    }
}

// ---------------------------------------------------------------------------
// Inverse DWT along a strided axis (x-pass, level-2 only now). No wrap needed.
// ---------------------------------------------------------------------------
template<int K, int NOUT, int INNER, bool HI>
__global__ void idwt_s(const float* __restrict__ lo, const float* __restrict__ hi,
                       float* __restrict__ out, unsigned total) {
    const float LO[8] = FLO;
    const float HIc[8] = FHI;
    unsigned g = blockIdx.x * blockDim.x + threadIdx.x;
    if (g >= total) return;
    unsigned ii = g % INNER;
    unsigned o  = g / INNER;
    const float* lp = lo + (size_t)o * (K * INNER) + ii;
    const float* hp = HI ? hi + (size_t)o * (K * INNER) + ii : lp;
    float*       op = out + (size_t)o * (NOUT * INNER) + ii;

    float wl[4], wh[4];
#pragma unroll
    for (int d = 0; d < 4; d++) {
        wl[d] = lp[(1 + d) * INNER];
        if (HI) wh[d] = hp[(1 + d) * INNER];
    }
#pragma unroll
    for (int i = 0; i < NOUT; i++) {
        const int par = i & 1;
        float acc = 0.f;
#pragma unroll
        for (int d = 0; d < 4; d++) {
            acc = fmaf(wl[d], LO[2 * d + 1 - par], acc);
            if (HI) acc = fmaf(wh[d], HIc[2 * d + 1 - par], acc);
        }
        op[i * INNER] = acc;
        if (par && (i + 1 < NOUT)) {
            int jn = i / 2 + 5;
#pragma unroll
            for (int d = 0; d < 3; d++) {
                wl[d] = wl[d + 1];
                if (HI) wh[d] = wh[d + 1];
            }
            wl[3] = lp[jn * INNER];
            if (HI) wh[3] = hp[jn * INNER];
        }
    }
}

// ---------------------------------------------------------------------------
// Level-1 forward, fused y+z, lo-only, paired outputs (R5 version).
// ---------------------------------------------------------------------------
__global__ void f1_yz(const float* __restrict__ in, float* __restrict__ out) {
    __shared__ float s0[64 * 64];
    __shared__ float s1[37 * 65];
    const float LO[8] = FLO;
    unsigned tid = threadIdx.x;
    size_t blk = blockIdx.x;
    const float* gp = in + blk * 4096;
#pragma unroll 4
    for (int t = tid; t < 4096; t += 256) s0[t] = gp[t];
    __syncthreads();
    for (int u = tid; u < 19 * 64; u += 256) {       // y-DWT pairs
        int z = u & 63, jp = u >> 6;
        float w[10];
#pragma unroll
        for (int t = 0; t < 10; t++) {
            int q = (4 * jp - 8 + t) & 63;
            w[t] = s0[q * 64 + z];
        }
        float a0 = 0.f, a1 = 0.f;
#pragma unroll
        for (int s = 0; s < 8; s++) {
            a0 = fmaf(LO[s], w[7 - s], a0);
            a1 = fmaf(LO[s], w[9 - s], a1);
        }
        s1[(2 * jp) * 65 + z] = a0;
        if (2 * jp + 1 < 37) s1[(2 * jp + 1) * 65 + z] = a1;
    }
    __syncthreads();
    float* op = out + blk * 1369;
    for (int u = tid; u < 37 * 19; u += 256) {       // z-DWT pairs
        int ph = u % 19, y = u / 19;
        float w[10];
#pragma unroll
        for (int t = 0; t < 10; t++) {
            int q = (4 * ph - 8 + t) & 63;
            w[t] = s1[y * 65 + q];
        }
        float a0 = 0.f, a1 = 0.f;
#pragma unroll
        for (int s = 0; s < 8; s++) {
            a0 = fmaf(LO[s], w[7 - s], a0);
            a1 = fmaf(LO[s], w[9 - s], a1);
        }
        op[y * 37 + 2 * ph] = a0;
        if (2 * ph + 1 < 37) op[y * 37 + 2 * ph + 1] = a1;
    }
}

// ---------------------------------------------------------------------------
// Level-2 forward, fused y+z, full (4 yz-bands), paired (R5 version).
// ---------------------------------------------------------------------------
__global__ void f2_yz(const float* __restrict__ in, float* __restrict__ out,
                      long long S2) {
    __shared__ float s0[37 * 37];
    __shared__ float sl[23 * 37];
    __shared__ float sh[23 * 37];
    const float LO[8] = FLO;
    const float HIc[8] = FHI;
    unsigned tid = threadIdx.x;
    size_t blk = blockIdx.x;
    const float* gp = in + blk * 1369;
#pragma unroll 3
    for (int t = tid; t < 1369; t += 256) s0[t] = gp[t];
    __syncthreads();
    for (int u = tid; u < 12 * 37; u += 256) {       // y-DWT lo+hi pairs
        int z = u % 37, jp = u / 37;
        float w[10];
#pragma unroll
        for (int t = 0; t < 10; t++) {
            int q = 4 * jp - 8 + t;
            if (q < 0) q += 37; else if (q >= 37) q -= 37;
            w[t] = s0[q * 37 + z];
        }
        float l0 = 0.f, h0 = 0.f, l1 = 0.f, h1 = 0.f;
#pragma unroll
        for (int s = 0; s < 8; s++) {
            l0 = fmaf(LO[s],  w[7 - s], l0);
            h0 = fmaf(HIc[s], w[7 - s], h0);
            l1 = fmaf(LO[s],  w[9 - s], l1);
            h1 = fmaf(HIc[s], w[9 - s], h1);
        }
        sl[(2 * jp) * 37 + z] = l0;
        sh[(2 * jp) * 37 + z] = h0;
        if (2 * jp + 1 < 23) {
            sl[(2 * jp + 1) * 37 + z] = l1;
            sh[(2 * jp + 1) * 37 + z] = h1;
        }
    }
    __syncthreads();
    for (int u = tid; u < 23 * 12; u += 256) {       // z-DWT pairs on both
        int ph = u % 12, y = u / 12;
        float wl[10], wh[10];
#pragma unroll
        for (int t = 0; t < 10; t++) {
            int q = 4 * ph - 8 + t;
            if (q < 0) q += 37; else if (q >= 37) q -= 37;
            wl[t] = sl[y * 37 + q];
            wh[t] = sh[y * 37 + q];
        }
        float ll0 = 0.f, lh0 = 0.f, hl0 = 0.f, hh0 = 0.f;
        float ll1 = 0.f, lh1 = 0.f, hl1 = 0.f, hh1 = 0.f;
#pragma unroll
        for (int s = 0; s < 8; s++) {
            ll0 = fmaf(LO[s],  wl[7 - s], ll0);  lh0 = fmaf(HIc[s], wl[7 - s], lh0);
            hl0 = fmaf(LO[s],  wh[7 - s], hl0);  hh0 = fmaf(HIc[s], wh[7 - s], hh0);
            ll1 = fmaf(LO[s],  wl[9 - s], ll1);  lh1 = fmaf(HIc[s], wl[9 - s], lh1);
            hl1 = fmaf(LO[s],  wh[9 - s], hl1);  hh1 = fmaf(HIc[s], wh[9 - s], hh1);
        }
        size_t b0 = blk * 529 + y * 23 + 2 * ph;
        out[b0]          = ll0;
        out[S2 + b0]     = lh0;
        out[2 * S2 + b0] = hl0;
        out[3 * S2 + b0] = hh0;
        if (2 * ph + 1 < 23) {
            out[b0 + 1]          = ll1;
            out[S2 + b0 + 1]     = lh1;
            out[2 * S2 + b0 + 1] = hl1;
            out[3 * S2 + b0 + 1] = hh1;
        }
    }
}

// ---------------------------------------------------------------------------
// Level-2 inverse, fused z+y, full, paired (R5 version).
// ---------------------------------------------------------------------------
__global__ void i2_yz(const float* __restrict__ in, float* __restrict__ out,
                      long long S2) {
    __shared__ float si[4 * 529];
    __shared__ float sl[23 * 37];
    __shared__ float sh[23 * 37];
    const float LO[8] = FLO;
    const float HIc[8] = FHI;
    unsigned tid = threadIdx.x;
    size_t blk = blockIdx.x;
    for (int t = tid; t < 4 * 529; t += 256) {
        int slot = t / 529, r = t % 529;
        si[t] = in[(size_t)slot * S2 + blk * 529 + r];
    }
    __syncthreads();
    for (int u = tid; u < 23 * 19; u += 256) {       // z-IDWT, both dy rows
        int m = u % 19, y = u / 19;
        int js = m + 1;
        float a0 = 0.f, a1 = 0.f, b0 = 0.f, b1 = 0.f;
#pragma unroll
        for (int d = 0; d < 4; d++) {
            int q = y * 23 + js + d;
            float v0 = si[q],           v1 = si[529 + q];
            float v2 = si[2 * 529 + q], v3 = si[3 * 529 + q];
            a0 = fmaf(v0, LO[2 * d + 1], a0);  a0 = fmaf(v1, HIc[2 * d + 1], a0);
            a1 = fmaf(v0, LO[2 * d],     a1);  a1 = fmaf(v1, HIc[2 * d],     a1);
            b0 = fmaf(v2, LO[2 * d + 1], b0);  b0 = fmaf(v3, HIc[2 * d + 1], b0);
            b1 = fmaf(v2, LO[2 * d],     b1);  b1 = fmaf(v3, HIc[2 * d],     b1);
        }
        sl[y * 37 + 2 * m] = a0;  sh[y * 37 + 2 * m] = b0;
        if (2 * m + 1 < 37) {
            sl[y * 37 + 2 * m + 1] = a1;  sh[y * 37 + 2 * m + 1] = b1;
        }
    }
    __syncthreads();
    float* op = out + blk * 1369;
    for (int u = tid; u < 19 * 37; u += 256) {       // y-IDWT pairs
        int z = u % 37, m = u / 37;
        int js = m + 1;
        float a0 = 0.f, a1 = 0.f;
#pragma unroll
        for (int d = 0; d < 4; d++) {
            float vl = sl[(js + d) * 37 + z];
            float vh = sh[(js + d) * 37 + z];
            a0 = fmaf(vl, LO[2 * d + 1], a0);  a0 = fmaf(vh, HIc[2 * d + 1], a0);
            a1 = fmaf(vl, LO[2 * d],     a1);  a1 = fmaf(vh, HIc[2 * d],     a1);
        }
        op[(2 * m) * 37 + z] = a0;
        if (2 * m + 1 < 37) op[(2 * m + 1) * 37 + z] = a1;
    }
}

// ---------------------------------------------------------------------------
// Level-1 inverse, FUSED x+z+y, lo-only. One block per (bc, xb) with
// xb in [0,16): covers output x-slices xo = 4xb..4xb+3.
// Reads the 5 shared source slices (js union = [2xb+1, 2xb+5]) once,
// then per xo: x-IDWT combine -> z-IDWT -> y-IDWT -> direct output write.
// Replaces idwt_s<37,64,1369> + i1_yz (no (320,64,37,37) intermediate).
// ---------------------------------------------------------------------------
__global__ void i1x_yz(const float* __restrict__ in, float* __restrict__ out) {
    __shared__ float ss[5 * 1369];   // 5 source x-slices (37y x 37z each)
    __shared__ float s0[1369];       // x-combined slice for current xo
    __shared__ float s1[37 * 65];    // z-IDWT result (37y x 64z, padded)
    const float LO[8] = FLO;
    unsigned tid = threadIdx.x;
    unsigned bc = blockIdx.x >> 4;         // /16
    unsigned xb = blockIdx.x & 15;
    int j0 = 2 * (int)xb + 1;              // first source slice (<= 31; +4 <= 35)

    const float* gp = in + ((size_t)bc * 37 + j0) * 1369;
#pragma unroll 2
    for (int t = tid; t < 5 * 1369; t += 256) ss[t] = gp[t];   // coalesced
    __syncthreads();

#pragma unroll
    for (int c = 0; c < 4; c++) {
        int xo  = 4 * (int)xb + c;
        int par = c & 1;
        int off = (c >> 1) * 1369;         // slice window start within ss

        // x-IDWT: s0[t] = sum_d ss[off + d*1369 + t] * LO[2d+1-par]
        for (int t = tid; t < 1369; t += 256) {
            float a = 0.f;
#pragma unroll
            for (int d = 0; d < 4; d++) {
                float fl = par ? LO[2 * d] : LO[2 * d + 1];
                a = fmaf(ss[off + d * 1369 + t], fl, a);
            }
            s0[t] = a;
        }
        __syncthreads();

        // z-IDWT, paired: 37 y x 32 pairs (R5 i1_yz stage).
        for (int u = tid; u < 37 * 32; u += 256) {
            int m = u & 31, y = u >> 5;
            int js = m + 1;
            float a0 = 0.f, a1 = 0.f;
#pragma unroll
            for (int d = 0; d < 4; d++) {
                float v = s0[y * 37 + js + d];
                a0 = fmaf(v, LO[2 * d + 1], a0);
                a1 = fmaf(v, LO[2 * d],     a1);
            }
            s1[y * 65 + 2 * m]     = a0;
            s1[y * 65 + 2 * m + 1] = a1;
        }
        __syncthreads();

        // y-IDWT, paired: 32 pairs x 64 z; direct coalesced output write.
        float* op = out + ((size_t)bc * 64 + xo) * 4096;
        for (int u = tid; u < 32 * 64; u += 256) {
            int z = u & 63, m = u >> 6;
            int js = m + 1;
            float a0 = 0.f, a1 = 0.f;
#pragma unroll
            for (int d = 0; d < 4; d++) {
                float v = s1[(js + d) * 65 + z];
                a0 = fmaf(v, LO[2 * d + 1], a0);
                a1 = fmaf(v, LO[2 * d],     a1);
            }
            op[(2 * m) * 64 + z]     = a0;
            op[(2 * m + 1) * 64 + z] = a1;
        }
        __syncthreads();
    }
}

// ---------------------------------------------------------------------------
// Channel mix, ALL 8 bands in one launch (blockIdx.y = band).
// ---------------------------------------------------------------------------
__global__ void chanmix_all(const float* __restrict__ in,
                            float* __restrict__ out, long long SBl,
                            const float* __restrict__ w0, const float* __restrict__ w1,
                            const float* __restrict__ w2, const float* __restrict__ w3,
                            const float* __restrict__ w4, const float* __restrict__ w5,
                            const float* __restrict__ w6, const float* __restrict__ w7) {
    __shared__ float s_in[320][32];
    int k = blockIdx.y;
    const float* w;
    switch (k) {
        case 0: w = w0; break; case 1: w = w1; break;
        case 2: w = w2; break; case 3: w = w3; break;
        case 4: w = w4; break; case 5: w = w5; break;
        case 6: w = w6; break; default: w = w7; break;
    }
    const float* bin  = in  + (long long)k * SBl;
    float*       bout = out + (long long)k * SBl;

    int lane = threadIdx.x;
    int ty   = threadIdx.y;
    int v    = blockIdx.x * 32 + lane;
    bool valid = v < NV;
    int vc = valid ? v : (NV - 1);

    for (int r = ty; r < 320; r += 8)
        s_in[r][lane] = bin[(long long)r * NV + vc];
    __syncthreads();

    float acc[5][8];
#pragma unroll
    for (int a = 0; a < 5; a++)
#pragma unroll
        for (int b = 0; b < 8; b++) acc[a][b] = 0.f;

#pragma unroll 2
    for (int i = 0; i < 40; i += 2) {
        float xv0[8], xv1[8];
#pragma unroll
        for (int b = 0; b < 8; b++) {
            xv0[b] = s_in[b * 40 + i][lane];
            xv1[b] = s_in[b * 40 + i + 1][lane];
        }
        float wv0[5], wv1[5];
#pragma unroll
        for (int oo = 0; oo < 5; oo++) {
            int o = ty + oo * 8;
            wv0[oo] = w[((long long)i * 40 + o) * NV + vc];
            wv1[oo] = w[((long long)(i + 1) * 40 + o) * NV + vc];
        }
#pragma unroll
        for (int oo = 0; oo < 5; oo++)
#pragma unroll
            for (int b = 0; b < 8; b++) {
                acc[oo][b] = fmaf(xv0[b], wv0[oo], acc[oo][b]);
                acc[oo][b] = fmaf(xv1[b], wv1[oo], acc[oo][b]);
            }
    }
    if (!valid) return;
#pragma unroll
    for (int oo = 0; oo < 5; oo++) {
        int o = ty + oo * 8;
#pragma unroll
        for (int b = 0; b < 8; b++)
            bout[((long long)b * 40 + o) * NV + v] = acc[oo][b];
    }
}

// ---------------------------------------------------------------------------
extern "C" void kernel_launch(void* const* d_in, const int* in_sizes, int n_in,
                              void* d_out, int out_size) {
    const float* x = (const float*)d_in[0];
    float* out = (float*)d_out;

    float *b1, *b2;
    cudaGetSymbolAddress((void**)&b1, g_buf1);
    cudaGetSymbolAddress((void**)&b2, g_buf2);

    const long long S2  = 6263360LL;   // 320*37*23*23 (per yz-band volume)
    const long long SBl = 3893440LL;   // 320*23*23*23 (per final band volume)

    auto g = [](unsigned t) { return (t + 255u) / 256u; };

    // --- Level-1 forward: fused yz (lo), then x (lo) ------------------------
    f1_yz<<<320 * 64, 256>>>(x, b1);                        // -> (320,64,37,37)
    { unsigned T = 320u * 1369u;                            // -> (320,37,37,37)
      dwt_s<64, 1369, false><<<g(T), 256>>>(b1, b2, nullptr, T); }

    // --- Level-2 forward: fused yz (4 bands), then x (lo+hi over all 4) -----
    f2_yz<<<320 * 37, 256>>>(b2, b1, S2);                   // -> 4x(320,37,23,23)
    { unsigned T = 1280u * 529u;                            // -> 8x(320,23,23,23)
      dwt_s<37, 529, true><<<g(T), 256>>>(b1, b2, b2 + 4 * SBl, T); }

    // --- Channel mix: all 8 bands in one launch (slot == weight index k) ----
    chanmix_all<<<dim3((NV + 31) / 32, 8), dim3(32, 8)>>>(
        b2, b1, SBl,
        (const float*)d_in[1], (const float*)d_in[2],
        (const float*)d_in[3], (const float*)d_in[4],
        (const float*)d_in[5], (const float*)d_in[6],
        (const float*)d_in[7], (const float*)d_in[8]);

    // --- Level-2 inverse: x (lo+hi over all 4), then fused zy ---------------
    { unsigned T = 1280u * 529u;                            // -> 4x(320,37,23,23)
      idwt_s<23, 37, 529, true><<<g(T), 256>>>(b1, b1 + 4 * SBl, b2, T); }
    i2_yz<<<320 * 37, 256>>>(b2, b1, S2);                   // -> (320,37,37,37)

    // --- Level-1 inverse: FUSED x+zy (lo), no intermediate ------------------
    i1x_yz<<<320 * 16, 256>>>(b1, out);                     // -> (320,64,64,64)
}